// round 11
// baseline (speedup 1.0000x reference)
#include <cuda_runtime.h>
#include <cstdint>

// DEMA decomposition: x (32, 2048, 512) f32 -> (res, ma) each same shape.
//   s0 = x[:,0,:]; b0 = x[:,1,:] - s0
//   s_t = a*x_t + (1-a)*(s_{t-1} + b_{t-1})
//   b_t = be*(s_t - s_{t-1}) + (1-be)*b_{t-1}
//   ma = [s0..s_{T-1}], res = x - ma
//
// Chunked scan: spectral radius sqrt(0.7)~0.837 -> warmup W gives state error
// ~0.837^W. Measured rel_err: W=96 -> 1.1e-7, W=64 -> 1.7e-5, W=48 -> 2.9e-4.
//
// R11 = R8 champion (CHUNK=64, WARM=48, (s,u) 2-FMA-chain step, plain main
// loads, __stcs stores, unroll-4 main loop) + warmup loads pinned in L2 via
// createpolicy.fractional.L2::evict_last + ld.global.L2::cache_hint
// (the bare ld.global.L2::evict_last.v4.f32 form is rejected by ptxas on
// sm_103 -- policy-register form is the architected path for 16B vectors).
// Rationale: warmup is the FIRST toucher of each chunk's tail lines (96 MB
// retained set); R8 measured 56 MB of those evicted by store pressure before
// the owner's late main-pass read. evict_last outranks the evict_first
// store stream in L2 replacement.

#define ALPHA 0.3f
#define BETA  0.3f

#define BDIM 32
#define TDIM 2048
#define FDIM 512

#define CHUNK 64
#define WARM  48
#define NCHUNK (TDIM / CHUNK)   // 32
#define F4    (FDIM / 4)        // 128

// evict_last policy-hinted 16B load.
__device__ __forceinline__ float4 ldg_evict_last(const float4* p, uint64_t pol) {
    float4 v;
    asm volatile("ld.global.L2::cache_hint.v4.f32 {%0,%1,%2,%3}, [%4], %5;"
        : "=f"(v.x), "=f"(v.y), "=f"(v.z), "=f"(v.w)
        : "l"(p), "l"(pol));
    return v;
}

// (s,u) step, u = s + b:
//   s' = ALPHA*x + (1-ALPHA)*u
//   u' = (1+BETA)*s' + ((1-BETA)*u - s)
__device__ __forceinline__ void dema_step(float4& s, float4& u, const float4 xt) {
    float4 sn, tmp;
    tmp.x = fmaf(1.0f - BETA, u.x, -s.x);
    tmp.y = fmaf(1.0f - BETA, u.y, -s.y);
    tmp.z = fmaf(1.0f - BETA, u.z, -s.z);
    tmp.w = fmaf(1.0f - BETA, u.w, -s.w);
    sn.x = fmaf(1.0f - ALPHA, u.x, ALPHA * xt.x);
    sn.y = fmaf(1.0f - ALPHA, u.y, ALPHA * xt.y);
    sn.z = fmaf(1.0f - ALPHA, u.z, ALPHA * xt.z);
    sn.w = fmaf(1.0f - ALPHA, u.w, ALPHA * xt.w);
    u.x = fmaf(1.0f + BETA, sn.x, tmp.x);
    u.y = fmaf(1.0f + BETA, sn.y, tmp.y);
    u.z = fmaf(1.0f + BETA, sn.z, tmp.z);
    u.w = fmaf(1.0f + BETA, sn.w, tmp.w);
    s = sn;
}

__global__ void __launch_bounds__(F4, 8) dema_kernel(
    const float* __restrict__ x, float* __restrict__ out)
{
    const int c  = blockIdx.x;      // chunk 0..31
    const int b  = blockIdx.y;      // batch 0..31
    const int f4 = threadIdx.x;     // 0..127

    const float4* __restrict__ xb =
        reinterpret_cast<const float4*>(x + (size_t)b * TDIM * FDIM) + f4;
    float4* __restrict__ res =
        reinterpret_cast<float4*>(out) + (size_t)b * TDIM * F4 + f4;
    float4* __restrict__ ma =
        reinterpret_cast<float4*>(out + (size_t)BDIM * TDIM * FDIM)
        + (size_t)b * TDIM * F4 + f4;

    const int t0 = c * CHUNK;
    float4 s, u;   // u = s + b
    int t;

    if (c == 0) {
        // Exact init: s0 = x0, u0 = x1
        float4 x0 = xb[0];
        float4 x1 = xb[F4];
        s = x0;
        u = x1;
        __stcs(&ma[0], s);
        __stcs(&res[0], make_float4(0.0f, 0.0f, 0.0f, 0.0f));
        t = 1;
    } else {
        // Warmup over previous chunk's tail: first toucher of these lines.
        // evict_last policy pins them in L2 until the owner's main pass
        // reads them (stores are evict_first and cannot displace them).
        uint64_t pol;
        asm volatile("createpolicy.fractional.L2::evict_last.b64 %0, 1.0;"
                     : "=l"(pol));
        const int tw = t0 - WARM;
        float4 x0 = ldg_evict_last(&xb[tw * F4], pol);
        float4 x1 = ldg_evict_last(&xb[(tw + 1) * F4], pol);
        s = x0;
        u = x1;
        #pragma unroll 8
        for (int tt = tw + 1; tt < t0; ++tt) {
            float4 xt = ldg_evict_last(&xb[tt * F4], pol);
            dema_step(s, u, xt);
        }
        t = t0;
    }

    // Main pass: R8 champion shape -- plain loads, __stcs stores, unroll 4.
    const int tend = t0 + CHUNK;
    #pragma unroll 4
    for (; t < tend; ++t) {
        float4 xt = xb[t * F4];
        dema_step(s, u, xt);
        __stcs(&ma[t * F4], s);
        float4 r;
        r.x = xt.x - s.x; r.y = xt.y - s.y;
        r.z = xt.z - s.z; r.w = xt.w - s.w;
        __stcs(&res[t * F4], r);
    }
}

extern "C" void kernel_launch(void* const* d_in, const int* in_sizes, int n_in,
                              void* d_out, int out_size)
{
    const float* x = (const float*)d_in[0];
    float* out = (float*)d_out;
    dim3 grid(NCHUNK, BDIM);
    dema_kernel<<<grid, F4>>>(x, out);
}

// round 12
// speedup vs baseline: 1.1619x; 1.1619x over previous
#include <cuda_runtime.h>

// DEMA decomposition: x (32, 2048, 512) f32 -> (res, ma) each same shape.
//   s0 = x[:,0,:]; b0 = x[:,1,:] - s0
//   s_t = a*x_t + (1-a)*(s_{t-1} + b_{t-1})
//   b_t = be*(s_t - s_{t-1}) + (1-be)*b_{t-1}
//   ma = [s0..s_{T-1}], res = x - ma
//
// Chunked scan, warmup W: state error ~0.837^W (measured: W=48 -> 2.9e-4).
//
// R12: TWO-KERNEL SPLIT. All cache-hint attempts (R3/R4/R11) degraded the
// mixed-stream pump; R8's residual 56 MB DRAM excess is temporal (warmup
// inserts tail lines at kernel start, owner re-reads them at kernel end,
// 256 MB of stores evict them in between). Fix by restructuring time:
//   Kernel A: compute chunk entry states from W=48 warmup windows only.
//     Read-only (46 MB), no store pressure, and doubles as an L2 prefetch
//     of the tail lines for B (L2 persists across launches).
//   Kernel B: zero warmup -- load state, stream CHUNK=128 steps, write out.
//     Retained set is 46 MB (<< L2) and the re-read gap is short.
// Expected DRAM ~390 MB (vs R8's 440, floor 384); worst case ~= R8.

#define ALPHA 0.3f
#define BETA  0.3f

#define BDIM 32
#define TDIM 2048
#define FDIM 512

#define CHUNK 128
#define WARM  48
#define NCHUNK (TDIM / CHUNK)   // 16
#define F4    (FDIM / 4)        // 128

// Entry states for chunks 1..15: [chunk-1][batch][f4]
__device__ float4 g_state_s[(NCHUNK - 1) * BDIM * F4];
__device__ float4 g_state_u[(NCHUNK - 1) * BDIM * F4];

// (s,u) step, u = s + b:
//   s' = ALPHA*x + (1-ALPHA)*u
//   u' = (1+BETA)*s' + ((1-BETA)*u - s)
__device__ __forceinline__ void dema_step(float4& s, float4& u, const float4 xt) {
    float4 sn, tmp;
    tmp.x = fmaf(1.0f - BETA, u.x, -s.x);
    tmp.y = fmaf(1.0f - BETA, u.y, -s.y);
    tmp.z = fmaf(1.0f - BETA, u.z, -s.z);
    tmp.w = fmaf(1.0f - BETA, u.w, -s.w);
    sn.x = fmaf(1.0f - ALPHA, u.x, ALPHA * xt.x);
    sn.y = fmaf(1.0f - ALPHA, u.y, ALPHA * xt.y);
    sn.z = fmaf(1.0f - ALPHA, u.z, ALPHA * xt.z);
    sn.w = fmaf(1.0f - ALPHA, u.w, ALPHA * xt.w);
    u.x = fmaf(1.0f + BETA, sn.x, tmp.x);
    u.y = fmaf(1.0f + BETA, sn.y, tmp.y);
    u.z = fmaf(1.0f + BETA, sn.z, tmp.z);
    u.w = fmaf(1.0f + BETA, sn.w, tmp.w);
    s = sn;
}

// Kernel A: entry state for chunk c = blockIdx.x + 1 from its warmup window.
// Plain loads: read-only pass, also inserts the tail lines into L2 for B.
__global__ void __launch_bounds__(F4, 8) dema_states_kernel(
    const float* __restrict__ x)
{
    const int c  = blockIdx.x + 1;   // target chunk 1..15
    const int b  = blockIdx.y;
    const int f4 = threadIdx.x;

    const float4* __restrict__ xb =
        reinterpret_cast<const float4*>(x + (size_t)b * TDIM * FDIM) + f4;

    const int t0 = c * CHUNK;
    const int tw = t0 - WARM;

    float4 s = xb[tw * F4];
    float4 u = xb[(tw + 1) * F4];
    #pragma unroll 8
    for (int tt = tw + 1; tt < t0; ++tt) {
        float4 xt = xb[tt * F4];
        dema_step(s, u, xt);
    }

    const size_t si = ((size_t)(c - 1) * BDIM + b) * F4 + f4;
    g_state_s[si] = s;
    g_state_u[si] = u;
}

// Kernel B: pure streaming pass, no warmup.
__global__ void __launch_bounds__(F4, 8) dema_main_kernel(
    const float* __restrict__ x, float* __restrict__ out)
{
    const int c  = blockIdx.x;       // chunk 0..15
    const int b  = blockIdx.y;
    const int f4 = threadIdx.x;

    const float4* __restrict__ xb =
        reinterpret_cast<const float4*>(x + (size_t)b * TDIM * FDIM) + f4;
    float4* __restrict__ res =
        reinterpret_cast<float4*>(out) + (size_t)b * TDIM * F4 + f4;
    float4* __restrict__ ma =
        reinterpret_cast<float4*>(out + (size_t)BDIM * TDIM * FDIM)
        + (size_t)b * TDIM * F4 + f4;

    const int t0 = c * CHUNK;
    float4 s, u;
    int t;

    if (c == 0) {
        // Exact init: s0 = x0, u0 = x1
        float4 x0 = xb[0];
        float4 x1 = xb[F4];
        s = x0;
        u = x1;
        __stcs(&ma[0], s);
        __stcs(&res[0], make_float4(0.0f, 0.0f, 0.0f, 0.0f));
        t = 1;
    } else {
        const size_t si = ((size_t)(c - 1) * BDIM + b) * F4 + f4;
        s = g_state_s[si];
        u = g_state_u[si];
        t = t0;
    }

    const int tend = t0 + CHUNK;
    #pragma unroll 4
    for (; t < tend; ++t) {
        float4 xt = xb[t * F4];
        dema_step(s, u, xt);
        __stcs(&ma[t * F4], s);
        float4 r;
        r.x = xt.x - s.x; r.y = xt.y - s.y;
        r.z = xt.z - s.z; r.w = xt.w - s.w;
        __stcs(&res[t * F4], r);
    }
}

extern "C" void kernel_launch(void* const* d_in, const int* in_sizes, int n_in,
                              void* d_out, int out_size)
{
    const float* x = (const float*)d_in[0];
    float* out = (float*)d_out;
    dim3 gridA(NCHUNK - 1, BDIM);
    dema_states_kernel<<<gridA, F4>>>(x);
    dim3 gridB(NCHUNK, BDIM);
    dema_main_kernel<<<gridB, F4>>>(x, out);
}